// round 14
// baseline (speedup 1.0000x reference)
#include <cuda_runtime.h>
#include <cstdint>

// EnhancedLesionPenaltyLoss: pred (16,1,128,128,128) fp32 -> scalar loss.
// cp.async.bulk (UBLKCP) + mbarrier 4-stage smem ring: ONE bulk copy per
// plane-stage (8704B contiguous: 16 rows + halo row) replaces 512 LDG
// requests. Loads are register-free and structurally pipelined (3 planes in
// flight). h-neighbor comes from the halo row in the SAME stage (no dup
// global reads). d-neighbor: prev plane kept in registers.
// Grid: 16 batches x 8 strips(16 rows) x 4 zsegs(32 planes) = 512 x 256.
// Integer threshold compares + packed counters + integer max.
// Last block (atomic ticket) does the deterministic final reduction.

namespace {
constexpr int NB      = 16;
constexpr int STRIPS  = 8;
constexpr int ZSEGS   = 4;
constexpr int ZLEN    = 32;
constexpr int NBLK    = NB * STRIPS * ZSEGS;   // 512
constexpr int THREADS = 256;
constexpr int NACC    = 6;
constexpr int STAGES  = 4;
constexpr int STG_B   = 17 * 512;              // 8704 bytes (16 rows + halo)
constexpr unsigned U01 = 0x3C23D70Au;          // bits of 0.01f
constexpr unsigned U05 = 0x3F000000u;          // bits of 0.5f
}

__device__ float        g_part[NBLK * NACC];
__device__ unsigned int g_ticket = 0;

__device__ __forceinline__ void ldg256(float v[8], const char* p) {
    asm("ld.global.v8.f32 {%0,%1,%2,%3,%4,%5,%6,%7}, [%8];"
        : "=f"(v[0]), "=f"(v[1]), "=f"(v[2]), "=f"(v[3]),
          "=f"(v[4]), "=f"(v[5]), "=f"(v[6]), "=f"(v[7])
        : "l"(p));
}
__device__ __forceinline__ void mbar_init(unsigned mb, unsigned cnt) {
    asm volatile("mbarrier.init.shared.b64 [%0], %1;" :: "r"(mb), "r"(cnt)
                 : "memory");
}
__device__ __forceinline__ void mbar_expect_tx(unsigned mb, unsigned bytes) {
    asm volatile("mbarrier.arrive.expect_tx.shared.b64 _, [%0], %1;"
                 :: "r"(mb), "r"(bytes) : "memory");
}
__device__ __forceinline__ void bulk_g2s(unsigned dst, const void* src,
                                         unsigned bytes, unsigned mb) {
    asm volatile("cp.async.bulk.shared::cta.global"
                 ".mbarrier::complete_tx::bytes [%0], [%1], %2, [%3];"
                 :: "r"(dst), "l"(src), "r"(bytes), "r"(mb) : "memory");
}
__device__ __forceinline__ void mbar_wait(unsigned mb, unsigned ph) {
    unsigned done;
    asm volatile(
        "{\n\t.reg .pred p;\n\t"
        "mbarrier.try_wait.parity.acquire.cta.shared::cta.b64 p, [%1], %2;\n\t"
        "selp.b32 %0, 1, 0, p;\n\t}"
        : "=r"(done) : "r"(mb), "r"(ph) : "memory");
    if (!done) {
        asm volatile(
            "{\n\t.reg .pred P1;\n\t"
            "W%=:\n\t"
            "mbarrier.try_wait.parity.acquire.cta.shared::cta.b64 P1, [%0], %1, 0x989680;\n\t"
            "@P1 bra.uni D%=;\n\t"
            "bra.uni W%=;\n\t"
            "D%=:\n\t}"
            :: "r"(mb), "r"(ph) : "memory");
    }
}

struct St {
    unsigned cic;   // ci | (ch<<16)
    unsigned mxu;   // integer max (inputs non-negative)
    float sds, s1, s2;
};

__device__ __forceinline__ void body(const float v[8], const float prev[8],
                                     const float h[8],
                                     bool do_h, bool do_w, St& st) {
    const float nx = __shfl_down_sync(0xffffffffu, v[0], 1);
    float g = 0.f;
#pragma unroll
    for (int k = 1; k < 8; ++k) g += fabsf(v[k] - v[k - 1]);
    if (do_w) g += fabsf(nx - v[7]);
    if (do_h) {
#pragma unroll
        for (int k = 0; k < 8; ++k) g += fabsf(h[k] - v[k]);
    }
#pragma unroll
    for (int k = 0; k < 8; ++k) g += fabsf(v[k] - prev[k]);
    st.sds += g;
#pragma unroll
    for (int k = 0; k < 8; ++k) {
        const float    x  = v[k];
        const unsigned xu = __float_as_uint(x);
        if (xu > U01) {
            st.cic += 1u;
            st.s1  += x;
            st.s2   = fmaf(x, x, st.s2);
        }
        if (xu > U05) st.cic += 0x10000u;
        st.mxu = (xu > st.mxu) ? xu : st.mxu;
    }
}

__global__ __launch_bounds__(THREADS)
void lesion_fused(const float* __restrict__ pred, float* __restrict__ out) {
    __shared__ __align__(16) char sbuf[STAGES * STG_B];
    __shared__ uint64_t mbar[STAGES];
    __shared__ float red[8][NACC];
    __shared__ float fin[NB][NACC];
    __shared__ float lsh[NB];
    __shared__ unsigned int tick_sh;

    const int bid   = blockIdx.x;
    const int zseg  = bid & 3;
    const int strip = (bid >> 2) & 7;
    const int b     = bid >> 5;
    const int tid   = threadIdx.x;
    const int lane  = tid & 31;
    const int wid   = tid >> 5;

    const int col8 = tid & 15;             // 8-float column group
    const int rloc = tid >> 4;             // row within strip (0..15)
    const int grow = strip * 16 + rloc;
    const bool do_h = (grow < 127);
    const bool do_w = (col8 != 15);
    const int  z0   = zseg * ZLEN;

    // contiguous per-stage source: strip rows (+halo unless last strip)
    const unsigned stg_bytes = (strip == 7) ? 8192u : (unsigned)STG_B;
    const char* gbase = reinterpret_cast<const char*>(pred) +
                        (size_t)b * 8388608 + (size_t)strip * 8192;

    const unsigned smem0 = (unsigned)__cvta_generic_to_shared(sbuf);
    const unsigned mb0   = (unsigned)__cvta_generic_to_shared(mbar);

    if (tid == 0) {
#pragma unroll
        for (int s = 0; s < STAGES; ++s) mbar_init(mb0 + s * 8, 1);
    }
    __syncthreads();

    // prologue: stages 0..2
    if (tid == 0) {
#pragma unroll
        for (int k = 0; k < STAGES - 1; ++k) {
            mbar_expect_tx(mb0 + k * 8, stg_bytes);
            bulk_g2s(smem0 + k * STG_B,
                     gbase + (size_t)(z0 + k) * 65536, stg_bytes, mb0 + k * 8);
        }
    }

    // seed prev plane (z0-1) via one register v8 load (z0==0 -> self, diff 0)
    float prev[8];
    {
        const char* ps = reinterpret_cast<const char*>(pred) +
                         (size_t)b * 8388608 +
                         (size_t)((z0 > 0) ? z0 - 1 : 0) * 65536 +
                         (size_t)grow * 512 + (size_t)col8 * 32;
        ldg256(prev, ps);
    }

    St st = {0u, 0u, 0.f, 0.f, 0.f};
    const int f4v = rloc * 32 + col8 * 2;   // float4 index of v in stage
    const int f4h = f4v + 32;               // halo/neighbor row

    for (int i = 0; i < ZLEN; ++i) {
        const int s  = i & 3;
        const int ph = (i >> 2) & 1;
        mbar_wait(mb0 + s * 8, ph);

        const float4* st4 = reinterpret_cast<const float4*>(sbuf + s * STG_B);
        const float4 va = st4[f4v], vb = st4[f4v + 1];
        float4 ha, hb;
        if (do_h) { ha = st4[f4h]; hb = st4[f4h + 1]; }

        __syncthreads();   // all reads of stage (i-1)&3 and stage i complete

        if (tid == 0 && i + 3 < ZLEN) {
            const int sn = (i + 3) & 3;    // == (i-1)&3, safe after sync
            mbar_expect_tx(mb0 + sn * 8, stg_bytes);
            bulk_g2s(smem0 + sn * STG_B,
                     gbase + (size_t)(z0 + i + 3) * 65536, stg_bytes,
                     mb0 + sn * 8);
        }

        const float v[8] = {va.x, va.y, va.z, va.w, vb.x, vb.y, vb.z, vb.w};
        const float h[8] = {ha.x, ha.y, ha.z, ha.w, hb.x, hb.y, hb.z, hb.w};
        body(v, prev, h, do_h, do_w, st);
#pragma unroll
        for (int k = 0; k < 8; ++k) prev[k] = v[k];
    }

    // ---- block reduction (8 warps) ----
    float acc[NACC] = {(float)(st.cic & 0xFFFFu), (float)(st.cic >> 16),
                       __uint_as_float(st.mxu), st.sds, st.s1, st.s2};
#pragma unroll
    for (int k = 0; k < NACC; ++k) {
#pragma unroll
        for (int off = 16; off; off >>= 1) {
            const float t = __shfl_xor_sync(0xffffffffu, acc[k], off);
            acc[k] = (k == 2) ? fmaxf(acc[k], t) : (acc[k] + t);
        }
    }
    if (lane == 0) {
#pragma unroll
        for (int k = 0; k < NACC; ++k) red[wid][k] = acc[k];
    }
    __syncthreads();

    if (tid == 0) {
#pragma unroll
        for (int k = 0; k < NACC; ++k) {
            float r = red[0][k];
#pragma unroll
            for (int w = 1; w < 8; ++w)
                r = (k == 2) ? fmaxf(r, red[w][k]) : (r + red[w][k]);
            g_part[bid * NACC + k] = r;
        }
        __threadfence();
        tick_sh = atomicAdd(&g_ticket, 1u);
    }
    __syncthreads();
    if (tick_sh != (unsigned)(NBLK - 1)) return;

    // ---- last block: deterministic fixed-order final reduction ----
    __threadfence();

    constexpr int PER_B = STRIPS * ZSEGS;  // 32 partials per batch
    if (tid < NB * NACC) {
        const int fb = tid / NACC;
        const int fk = tid % NACC;
        const float* base = &g_part[(fb * PER_B) * NACC + fk];
        float r = base[0];
#pragma unroll
        for (int c2 = 1; c2 < PER_B; ++c2) {
            const float t = base[c2 * NACC];
            r = (fk == 2) ? fmaxf(r, t) : (r + t);
        }
        fin[fb][fk] = r;
    }
    __syncthreads();

    if (tid < NB) {
        const float cnt   = fin[tid][0];
        const float chigh = fin[tid][1];
        const float mxv   = fin[tid][2];
        const float sg    = fin[tid][3];
        const float S1    = fin[tid][4];
        const float S2    = fin[tid][5];

        const float invN   = 1.f / 2097152.f;        // 1/128^3
        const float invND3 = 1.f / 6242304.f;        // 1/(3*127*128*128)

        const float act = cnt * invN;
        float loss = fmaxf(0.005f - act, 0.f) * 15.f;

        const float high = chigh * invN;
        loss += fmaxf(high - 0.03f, 0.f) * 5.f;

        const float avg_grad = sg * invND3;
        if (mxv > 0.3f) loss += fminf(avg_grad, 1.f) * 5.f;

        const float cnt_safe = fmaxf(cnt, 1.f);
        const float m  = S1 / cnt_safe;
        const float sq = fmaxf(S2 - 2.f * m * S1 + m * m * cnt, 0.f);
        const bool gate = (act > 0.001f) && (cnt > 1.f);
        const float var = gate ? (sq / fmaxf(cnt - 1.f, 1.f)) : 1.f;
        const float rel_std = sqrtf(var) / (m + 1e-6f);
        const float pen = expf(-5.f * rel_std);
        loss += (gate ? pen : 0.f) * 7.f;

        lsh[tid] = loss;
    }
    __syncthreads();
    if (tid == 0) {
        float t = 0.f;
#pragma unroll
        for (int i = 0; i < NB; ++i) t += lsh[i];
        out[0] = t * (1.f / 16.f);
        g_ticket = 0;  // reset for next (graph-replayed) launch
    }
}

extern "C" void kernel_launch(void* const* d_in, const int* in_sizes, int n_in,
                              void* d_out, int out_size) {
    (void)in_sizes; (void)n_in; (void)out_size;
    const float* pred = (const float*)d_in[0];
    float* out = (float*)d_out;
    lesion_fused<<<NBLK, THREADS>>>(pred, out);
}

// round 15
// speedup vs baseline: 1.1953x; 1.1953x over previous
#include <cuda_runtime.h>

// EnhancedLesionPenaltyLoss: pred (16,1,128,128,128) fp32 -> scalar loss.
// Best structure (R13) + distance-2 rotating v-prefetch, h just-in-time:
// V[4] ring: iter k uses cur=V[k&3], prev=V[(k+3)&3] while planes k+1,k+2
// are in flight in the other two buffers -> each DRAM load has ~2 bodies of
// latency cover, zero register copies. h row (+512B) loads in-body: it is an
// L1 hit (same line was v-prefetched 2 iters earlier by the row+1 threads).
// Grid: 16 x 8 strips(16 rows) x 4 zsegs(32 planes) = 512 blocks x 256 thr,
// __launch_bounds__(256,4), single wave (592 >= 512).
// Integer threshold compares + packed counters + integer max.
// Last block (atomic ticket) does the deterministic final reduction.

namespace {
constexpr int NB      = 16;
constexpr int STRIPS  = 8;
constexpr int ZSEGS   = 4;
constexpr int ZLEN    = 32;
constexpr int NBLK    = NB * STRIPS * ZSEGS;   // 512
constexpr int THREADS = 256;
constexpr int NACC    = 6;               // cmin,cmax,max,sds,s1,s2
constexpr unsigned U01 = 0x3C23D70Au;    // bits of 0.01f
constexpr unsigned U05 = 0x3F000000u;    // bits of 0.5f
}

__device__ float        g_part[NBLK * NACC];
__device__ unsigned int g_ticket = 0;

__device__ __forceinline__ void ldg256(float v[8], const char* p) {
    asm("ld.global.v8.f32 {%0,%1,%2,%3,%4,%5,%6,%7}, [%8];"
        : "=f"(v[0]), "=f"(v[1]), "=f"(v[2]), "=f"(v[3]),
          "=f"(v[4]), "=f"(v[5]), "=f"(v[6]), "=f"(v[7])
        : "l"(p));
}

struct St {
    unsigned cic;   // ci | (ch<<16)
    unsigned mxu;   // integer max (inputs non-negative)
    float sds, s1, s2;
};

__device__ __forceinline__ void body(const float v[8], const float prev[8],
                                     const char* pz,
                                     bool do_h, bool do_w, St& st) {
    const float nx = __shfl_down_sync(0xffffffffu, v[0], 1);
    float g = 0.f;
#pragma unroll
    for (int k = 1; k < 8; ++k) g += fabsf(v[k] - v[k - 1]);
    if (do_w) g += fabsf(nx - v[7]);

    // h row: just-in-time load; L1-hit (line v-prefetched 2 iters ago by
    // the row+1 threads of this block).
    if (do_h) {
        float h[8];
        ldg256(h, pz + 512);
#pragma unroll
        for (int k = 0; k < 8; ++k) g += fabsf(h[k] - v[k]);
    }
#pragma unroll
    for (int k = 0; k < 8; ++k) g += fabsf(v[k] - prev[k]);
    st.sds += g;

#pragma unroll
    for (int k = 0; k < 8; ++k) {
        const float    x  = v[k];
        const unsigned xu = __float_as_uint(x);
        if (xu > U01) {
            st.cic += 1u;
            st.s1  += x;
            st.s2   = fmaf(x, x, st.s2);
        }
        if (xu > U05) st.cic += 0x10000u;
        st.mxu = (xu > st.mxu) ? xu : st.mxu;
    }
}

__global__ __launch_bounds__(THREADS, 4)
void lesion_fused(const float* __restrict__ pred, float* __restrict__ out) {
    const int bid   = blockIdx.x;
    const int zseg  = bid & 3;
    const int strip = (bid >> 2) & 7;
    const int b     = bid >> 5;
    const int tid   = threadIdx.x;
    const int lane  = tid & 31;
    const int wid   = tid >> 5;

    const int col8 = tid & 15;             // 8-float column group (0..15)
    const int rloc = tid >> 4;             // row within strip (0..15)
    const int grow = strip * 16 + rloc;    // global row (0..127)
    const bool do_h = (grow < 127);
    const bool do_w = (col8 != 15);
    const int  z0   = zseg * ZLEN;

    const char* pv = reinterpret_cast<const char*>(pred) +
                     (size_t)b * 8388608 + (size_t)z0 * 65536 +
                     (size_t)grow * 512 + (size_t)col8 * 32;

    St st = {0u, 0u, 0.f, 0.f, 0.f};

    float V[4][8];
    // Seed: V[3] = prev plane (z0-1; z0==0 -> plane 0, self-diff = 0).
    ldg256(V[3], (z0 > 0) ? (pv - 65536) : pv);
    ldg256(V[0], pv);                       // plane 0
    ldg256(V[1], pv + 65536);               // plane 1

    for (int i0 = 0; i0 < ZLEN; i0 += 4) {
#pragma unroll
        for (int k = 0; k < 4; ++k) {
            const int i  = i0 + k;
            // distance-2 prefetch into V[(k+2)&3] (free buffer; cur=k&3,
            // prev=(k+3)&3, inflight (k+1)&3 all distinct).
            const int zn = (i + 2 < ZLEN) ? (i + 2) : (ZLEN - 1);
            ldg256(V[(k + 2) & 3], pv + (size_t)zn * 65536);

            body(V[k & 3], V[(k + 3) & 3], pv + (size_t)i * 65536,
                 do_h, do_w, st);
        }
    }

    // ---- block reduction (8 warps) ----
    float acc[NACC] = {(float)(st.cic & 0xFFFFu), (float)(st.cic >> 16),
                       __uint_as_float(st.mxu), st.sds, st.s1, st.s2};
#pragma unroll
    for (int k = 0; k < NACC; ++k) {
#pragma unroll
        for (int off = 16; off; off >>= 1) {
            const float t = __shfl_xor_sync(0xffffffffu, acc[k], off);
            acc[k] = (k == 2) ? fmaxf(acc[k], t) : (acc[k] + t);
        }
    }
    __shared__ float red[8][NACC];
    __shared__ float fin[NB][NACC];
    __shared__ float lsh[NB];
    __shared__ unsigned int tick_sh;
    if (lane == 0) {
#pragma unroll
        for (int k = 0; k < NACC; ++k) red[wid][k] = acc[k];
    }
    __syncthreads();

    if (tid == 0) {
#pragma unroll
        for (int k = 0; k < NACC; ++k) {
            float r = red[0][k];
#pragma unroll
            for (int w = 1; w < 8; ++w)
                r = (k == 2) ? fmaxf(r, red[w][k]) : (r + red[w][k]);
            g_part[bid * NACC + k] = r;
        }
        __threadfence();
        tick_sh = atomicAdd(&g_ticket, 1u);
    }
    __syncthreads();
    if (tick_sh != (unsigned)(NBLK - 1)) return;

    // ---- last block: deterministic fixed-order final reduction ----
    __threadfence();  // acquire other blocks' g_part writes

    constexpr int PER_B = STRIPS * ZSEGS;  // 32 partials per batch
    if (tid < NB * NACC) {
        const int fb = tid / NACC;
        const int fk = tid % NACC;
        const float* base = &g_part[(fb * PER_B) * NACC + fk];
        float r = base[0];
#pragma unroll
        for (int c2 = 1; c2 < PER_B; ++c2) {
            const float t = base[c2 * NACC];
            r = (fk == 2) ? fmaxf(r, t) : (r + t);
        }
        fin[fb][fk] = r;
    }
    __syncthreads();

    if (tid < NB) {
        const float cnt   = fin[tid][0];
        const float chigh = fin[tid][1];
        const float mxv   = fin[tid][2];
        const float sg    = fin[tid][3];
        const float S1    = fin[tid][4];
        const float S2    = fin[tid][5];

        const float invN   = 1.f / 2097152.f;        // 1/128^3
        const float invND3 = 1.f / 6242304.f;        // 1/(3*127*128*128)

        const float act = cnt * invN;
        float loss = fmaxf(0.005f - act, 0.f) * 15.f;

        const float high = chigh * invN;
        loss += fmaxf(high - 0.03f, 0.f) * 5.f;

        const float avg_grad = sg * invND3;
        if (mxv > 0.3f) loss += fminf(avg_grad, 1.f) * 5.f;

        const float cnt_safe = fmaxf(cnt, 1.f);
        const float m  = S1 / cnt_safe;
        const float sq = fmaxf(S2 - 2.f * m * S1 + m * m * cnt, 0.f);
        const bool gate = (act > 0.001f) && (cnt > 1.f);
        const float var = gate ? (sq / fmaxf(cnt - 1.f, 1.f)) : 1.f;
        const float rel_std = sqrtf(var) / (m + 1e-6f);
        const float pen = expf(-5.f * rel_std);
        loss += (gate ? pen : 0.f) * 7.f;

        lsh[tid] = loss;
    }
    __syncthreads();
    if (tid == 0) {
        float t = 0.f;
#pragma unroll
        for (int i = 0; i < NB; ++i) t += lsh[i];
        out[0] = t * (1.f / 16.f);
        g_ticket = 0;  // reset for next (graph-replayed) launch
    }
}

extern "C" void kernel_launch(void* const* d_in, const int* in_sizes, int n_in,
                              void* d_out, int out_size) {
    (void)in_sizes; (void)n_in; (void)out_size;
    const float* pred = (const float*)d_in[0];
    float* out = (float*)d_out;
    lesion_fused<<<NBLK, THREADS>>>(pred, out);
}